// round 16
// baseline (speedup 1.0000x reference)
#include <cuda_runtime.h>
#include <cstdint>

#define T_ 256
#define B_ 64
#define E_ 300
#define H_ 256
#define G_ 1024
#define K_ 25

// ---------------- device scratch (static: no allocations allowed) ----------
__device__ float g_xg[2][T_][B_][G_];   // pre-activation gates
__device__ float g_h [2][T_][B_][H_];   // hidden states, both directions
__device__ float g_em[B_][T_][K_];      // emissions
__device__ float g_nll[B_];             // per-sequence (logZ - num)
__device__ unsigned g_bar_count[2];
__device__ volatile unsigned g_bar_phase[2];

__device__ __forceinline__ unsigned f2tf32(float f) {
    unsigned u; asm("cvt.rna.tf32.f32 %0, %1;" : "=r"(u) : "f"(f)); return u;
}

__device__ __forceinline__ void mma_tf32(
    float& c0, float& c1, float& c2, float& c3,
    unsigned a0, unsigned a1, unsigned a2, unsigned a3,
    unsigned b0, unsigned b1)
{
    asm volatile(
        "mma.sync.aligned.m16n8k8.row.col.f32.tf32.tf32.f32 "
        "{%0,%1,%2,%3},{%4,%5,%6,%7},{%8,%9},{%0,%1,%2,%3};"
        : "+f"(c0), "+f"(c1), "+f"(c2), "+f"(c3)
        : "r"(a0), "r"(a1), "r"(a2), "r"(a3), "r"(b0), "r"(b1));
}

// =====================================================================
// Kernel 1: embedding gather + xg GEMM — tf32 mma.sync (R9 record source).
// Also zeroes the k_lstm barrier state (stream-ordered).
// =====================================================================
__global__ __launch_bounds__(256) void k_xg(
    const int* __restrict__ sentence, const float* __restrict__ emb,
    const float* __restrict__ wf, const float* __restrict__ wb,
    const float* __restrict__ bihf, const float* __restrict__ bhhf,
    const float* __restrict__ bihb, const float* __restrict__ bhhb)
{
    __shared__ float A_s[128][36];   // tf32 bit patterns, pitch 36
    __shared__ float B_s[64][36];
    const int tid  = threadIdx.x;
    const int nblk = blockIdx.x * 64;
    const int mblk = blockIdx.y * 128;

    if (blockIdx.x == 0 && blockIdx.y == 0 && tid == 0) {
        g_bar_count[0] = 0u; g_bar_count[1] = 0u;
        g_bar_phase[0] = 0u; g_bar_phase[1] = 0u;
    }

    const int ar = tid >> 1;
    const int m_row = mblk + ar;
    const float* aptr = emb + (size_t)sentence[(m_row & 63) * T_ + (m_row >> 6)] * E_;

    const int wid = tid >> 5, lane = tid & 31;
    const int gid = lane >> 2, tig = lane & 3;
    const int wm = (wid >> 1) * 32;
    const int wn = (wid & 1) * 32;

    float acc[2][4][4];
    #pragma unroll
    for (int mi = 0; mi < 2; ++mi)
        #pragma unroll
        for (int ni = 0; ni < 4; ++ni)
            #pragma unroll
            for (int q = 0; q < 4; ++q) acc[mi][ni][q] = 0.f;

    for (int k0 = 0; k0 < 320; k0 += 32) {
        __syncthreads();
        #pragma unroll
        for (int q = 0; q < 4; ++q) {
            int kc = (tid & 1) * 16 + q * 4;
            int kg = k0 + kc;
            float4 v = make_float4(0.f, 0.f, 0.f, 0.f);
            if (kg + 4 <= E_) v = *(const float4*)(aptr + kg);
            A_s[ar][kc + 0] = __uint_as_float(f2tf32(v.x));
            A_s[ar][kc + 1] = __uint_as_float(f2tf32(v.y));
            A_s[ar][kc + 2] = __uint_as_float(f2tf32(v.z));
            A_s[ar][kc + 3] = __uint_as_float(f2tf32(v.w));
        }
        #pragma unroll
        for (int i2 = 0; i2 < 2; ++i2) {
            int i  = tid + i2 * 256;
            int br = i >> 3;
            int kc = (i & 7) * 4;
            int n  = nblk + br;
            const float* bp = (n < G_) ? (wf + (size_t)n * E_)
                                       : (wb + (size_t)(n - G_) * E_);
            int kg = k0 + kc;
            float4 v = make_float4(0.f, 0.f, 0.f, 0.f);
            if (kg + 4 <= E_) v = *(const float4*)(bp + kg);
            B_s[br][kc + 0] = __uint_as_float(f2tf32(v.x));
            B_s[br][kc + 1] = __uint_as_float(f2tf32(v.y));
            B_s[br][kc + 2] = __uint_as_float(f2tf32(v.z));
            B_s[br][kc + 3] = __uint_as_float(f2tf32(v.w));
        }
        __syncthreads();

        #pragma unroll
        for (int s = 0; s < 4; ++s) {
            int kk = s * 8;
            unsigned a[2][4];
            #pragma unroll
            for (int mi = 0; mi < 2; ++mi) {
                const float* ap0 = &A_s[wm + 16 * mi + gid][kk + tig];
                const float* ap1 = &A_s[wm + 16 * mi + gid + 8][kk + tig];
                a[mi][0] = __float_as_uint(ap0[0]);
                a[mi][1] = __float_as_uint(ap1[0]);
                a[mi][2] = __float_as_uint(ap0[4]);
                a[mi][3] = __float_as_uint(ap1[4]);
            }
            unsigned bf[4][2];
            #pragma unroll
            for (int ni = 0; ni < 4; ++ni) {
                const float* bp = &B_s[wn + 8 * ni + gid][kk + tig];
                bf[ni][0] = __float_as_uint(bp[0]);
                bf[ni][1] = __float_as_uint(bp[4]);
            }
            #pragma unroll
            for (int mi = 0; mi < 2; ++mi)
                #pragma unroll
                for (int ni = 0; ni < 4; ++ni)
                    mma_tf32(acc[mi][ni][0], acc[mi][ni][1],
                             acc[mi][ni][2], acc[mi][ni][3],
                             a[mi][0], a[mi][1], a[mi][2], a[mi][3],
                             bf[ni][0], bf[ni][1]);
        }
    }

    const int dirn = nblk >> 10;
    const int gnb  = nblk & 1023;
    const float* bi = dirn ? bihb : bihf;
    const float* bh = dirn ? bhhb : bhhf;
    float* base = &g_xg[dirn][0][0][0];

    float2 bias2[4];
    #pragma unroll
    for (int ni = 0; ni < 4; ++ni) {
        int gb = gnb + wn + 8 * ni + 2 * tig;
        bias2[ni] = make_float2(bi[gb] + bh[gb], bi[gb + 1] + bh[gb + 1]);
    }

    #pragma unroll
    for (int mi = 0; mi < 2; ++mi) {
        int m0r = mblk + wm + 16 * mi + gid;
        #pragma unroll
        for (int ni = 0; ni < 4; ++ni) {
            int gn = gnb + wn + 8 * ni + 2 * tig;
            float2 v0 = make_float2(acc[mi][ni][0] + bias2[ni].x,
                                    acc[mi][ni][1] + bias2[ni].y);
            float2 v1 = make_float2(acc[mi][ni][2] + bias2[ni].x,
                                    acc[mi][ni][3] + bias2[ni].y);
            *(float2*)(base + (size_t)m0r * G_ + gn)       = v0;
            *(float2*)(base + (size_t)(m0r + 8) * G_ + gn) = v1;
        }
    }
}

// =====================================================================
// Kernel 2: persistent BiLSTM recurrence — tf32 mma.sync, 64 blocks/dir,
// W fragments in registers, pipelined tf32 h staging, atomic-counter
// grid barrier. (R9 record source.)
// =====================================================================
__device__ __forceinline__ float sigmoidf_(float x) {
    return 1.f / (1.f + __expf(-x));
}

__global__ __launch_bounds__(256, 1) void k_lstm(
    const float* __restrict__ whf, const float* __restrict__ whb)
{
    extern __shared__ float sm[];
    float* h_s = sm;              // [64][260] tf32-truncated h values
    float* Y_s = sm + 64 * 260;   // [64][18]  gate pre-activations
    const int tid = threadIdx.x;
    const int dir = blockIdx.x >> 6;
    const int cbk = blockIdx.x & 63;
    const int c0  = cbk * 4;
    const float* wh = dir ? whb : whf;

    const int wid = tid >> 5, lane = tid & 31;
    const int gid = lane >> 2, tig = lane & 3;
    const int m0 = (wid >> 1) * 16;    // warp's 16 batch rows
    const int n0 = (wid & 1) * 8;      // warp's 8 local gate cols

    const int l = n0 + gid;
    const float* wr = wh + (size_t)((l >> 2) * 256 + c0 + (l & 3)) * H_;
    unsigned wb0[32], wb1[32];
    #pragma unroll
    for (int s = 0; s < 32; ++s) {
        wb0[s] = f2tf32(__ldg(wr + s * 8 + tig));
        wb1[s] = f2tf32(__ldg(wr + s * 8 + tig + 4));
    }

    const int b = tid >> 2, c = tid & 3;
    float creg = 0.f;
    unsigned phase = 0;

    for (int step = 0; step < T_; ++step) {
        const int t = dir ? (T_ - 1 - step) : step;

        const float* xg = &g_xg[dir][t][b][0];
        float ai = __ldg(xg +       c0 + c);
        float af = __ldg(xg + 256 + c0 + c);
        float ag = __ldg(xg + 512 + c0 + c);
        float ao = __ldg(xg + 768 + c0 + c);

        float acc0 = 0.f, acc1 = 0.f, acc2 = 0.f, acc3 = 0.f;

        if (step > 0) {
            const int tp = dir ? (t + 1) : (t - 1);
            const float4* src = (const float4*)&g_h[dir][tp][0][0];
            float4 pre[4];
            #pragma unroll
            for (int q = 0; q < 4; ++q) {
                int u = q * 256 + tid;
                pre[q] = __ldcg(src + (u >> 4) * 64 + (u & 15));
            }
            #pragma unroll
            for (int cc = 0; cc < 4; ++cc) {
                #pragma unroll
                for (int q = 0; q < 4; ++q) {
                    int u = q * 256 + tid;
                    float4 v = pre[q];
                    float4 w;
                    w.x = __uint_as_float(f2tf32(v.x));
                    w.y = __uint_as_float(f2tf32(v.y));
                    w.z = __uint_as_float(f2tf32(v.z));
                    w.w = __uint_as_float(f2tf32(v.w));
                    *(float4*)&h_s[(u >> 4) * 260 + cc * 64 + (u & 15) * 4] = w;
                }
                float4 nxt[4];
                if (cc < 3) {
                    #pragma unroll
                    for (int q = 0; q < 4; ++q) {
                        int u = q * 256 + tid;
                        nxt[q] = __ldcg(src + (u >> 4) * 64 + (cc + 1) * 16 + (u & 15));
                    }
                }
                __syncthreads();
                #pragma unroll
                for (int s = 0; s < 8; ++s) {
                    int kk = cc * 64 + s * 8;
                    const float* ar = &h_s[(m0 + gid) * 260 + kk + tig];
                    unsigned a0 = __float_as_uint(ar[0]);
                    unsigned a2 = __float_as_uint(ar[4]);
                    unsigned a1 = __float_as_uint(ar[8 * 260]);
                    unsigned a3 = __float_as_uint(ar[8 * 260 + 4]);
                    int si = cc * 8 + s;
                    mma_tf32(acc0, acc1, acc2, acc3, a0, a1, a2, a3, wb0[si], wb1[si]);
                }
                #pragma unroll
                for (int q = 0; q < 4; ++q) pre[q] = nxt[q];
            }
            *(float2*)&Y_s[(m0 + gid) * 18 + n0 + 2 * tig]     = make_float2(acc0, acc1);
            *(float2*)&Y_s[(m0 + gid + 8) * 18 + n0 + 2 * tig] = make_float2(acc2, acc3);
        }
        __syncthreads();

        if (step > 0) {
            ai += Y_s[b * 18 +      c];
            af += Y_s[b * 18 +  4 + c];
            ag += Y_s[b * 18 +  8 + c];
            ao += Y_s[b * 18 + 12 + c];
        }

        float si = sigmoidf_(ai);
        float sf = sigmoidf_(af);
        float so = sigmoidf_(ao);
        float tg = tanhf(ag);
        creg = sf * creg + si * tg;
        g_h[dir][t][b][c0 + c] = so * tanhf(creg);

        // ---- atomic-counter grid barrier (per direction, 64 blocks) ----
        __syncthreads();
        if (tid == 0) {
            __threadfence();
            unsigned p = phase + 1;
            if (atomicAdd(&g_bar_count[dir], 1u) == 63u) {
                g_bar_count[dir] = 0u;
                __threadfence();
                g_bar_phase[dir] = p;
            } else {
                while (g_bar_phase[dir] < p) { }
                __threadfence();
            }
        }
        __syncthreads();
        phase++;
    }
}

// =====================================================================
// Kernel 3: emissions em[b][t][k] = [hf|hb] . W_out[k] + b_out[k]
// =====================================================================
__global__ __launch_bounds__(256) void k_em(
    const float* __restrict__ Wout, const float* __restrict__ bout)
{
    extern __shared__ float sm[];
    float* W_s = sm;              // [25][520]
    float* h_s = sm + 25 * 520;   // [16][520]
    const int tid = threadIdx.x;
    const int t = blockIdx.x;

    for (int i = tid; i < 25 * 512; i += 256) {
        int k = i >> 9, j = i & 511;
        W_s[k * 520 + j] = Wout[(size_t)k * 512 + j];
    }
    for (int bg = 0; bg < 4; ++bg) {
        __syncthreads();
        for (int i = tid; i < 16 * 512; i += 256) {
            int bb = i >> 9, j = i & 511;
            int bglob = bg * 16 + bb;
            float v = (j < 256) ? g_h[0][t][bglob][j] : g_h[1][t][bglob][j - 256];
            h_s[bb * 520 + j] = v;
        }
        __syncthreads();
        for (int idx = tid; idx < 16 * 25; idx += 256) {
            int bb = idx / 25, k = idx % 25;
            const float* hr = &h_s[bb * 520];
            const float* wr = &W_s[k * 520];
            float dot = 0.f;
            #pragma unroll 8
            for (int j = 0; j < 512; j += 4) {
                float4 hv = *(const float4*)(hr + j);
                float4 wv = *(const float4*)(wr + j);
                dot += hv.x * wv.x + hv.y * wv.y + hv.z * wv.z + hv.w * wv.w;
            }
            g_em[bg * 16 + bb][t][k] = dot + bout[k];
        }
    }
}

// =====================================================================
// Kernel 4: CRF — single shfl pass + exact tree max + 5-way partial sums.
// trans stays in smem (avoids the R6 register-spill trap). Max is exactly
// associative -> tree reduction is bit-identical to the serial chain.
// =====================================================================
__global__ __launch_bounds__(128) void k_crf(
    const int* __restrict__ labels,
    const float* __restrict__ start_t,
    const float* __restrict__ end_t,
    const float* __restrict__ trans)
{
    __shared__ float tr_s[25 * 26 + 8];
    __shared__ float st_s[25], en_s[25];
    const int tid = threadIdx.x;
    for (int i = tid; i < 625; i += 128)
        tr_s[(i / 25) * 26 + (i % 25)] = trans[i];
    if (tid < 25) { st_s[tid] = start_t[tid]; en_s[tid] = end_t[tid]; }
    __syncthreads();

    const int w = tid >> 5, lane = tid & 31;
    const int b = blockIdx.x * 4 + w;
    const int lj = (lane < 25) ? lane : 24;
    const float* em_b = &g_em[b][0][0];

    float alpha = (lane < 25) ? (st_s[lane] + em_b[lane]) : -1e30f;

    for (int t = 1; t < T_; ++t) {
        float e = (lane < 25) ? em_b[t * 25 + lane] : 0.f;

        // single shfl pass: v[i] = alpha_i + trans[i][lj]
        float v[25];
        #pragma unroll
        for (int i = 0; i < 25; ++i)
            v[i] = __shfl_sync(0xffffffffu, alpha, i) + tr_s[i * 26 + lj];

        // exact tree max (depth 5)
        float m01 = fmaxf(v[0], v[1]),   m23 = fmaxf(v[2], v[3]);
        float m45 = fmaxf(v[4], v[5]),   m67 = fmaxf(v[6], v[7]);
        float m89 = fmaxf(v[8], v[9]),   mab = fmaxf(v[10], v[11]);
        float mcd = fmaxf(v[12], v[13]), mef = fmaxf(v[14], v[15]);
        float mgh = fmaxf(v[16], v[17]), mij = fmaxf(v[18], v[19]);
        float mkl = fmaxf(v[20], v[21]), mmn = fmaxf(v[22], v[23]);
        float q0 = fmaxf(m01, m23), q1 = fmaxf(m45, m67);
        float q2 = fmaxf(m89, mab), q3 = fmaxf(mcd, mef);
        float q4 = fmaxf(mgh, mij), q5 = fmaxf(mkl, mmn);
        float r0 = fmaxf(q0, q1), r1 = fmaxf(q2, q3), r2 = fmaxf(q4, q5);
        float m = fmaxf(fmaxf(r0, r1), fmaxf(r2, v[24]));

        // 5-way partial sums of exp(v - m)
        float s0 = 0.f, s1 = 0.f, s2 = 0.f, s3 = 0.f, s4 = 0.f;
        #pragma unroll
        for (int i = 0; i < 25; i += 5) {
            s0 += __expf(v[i]     - m);
            s1 += __expf(v[i + 1] - m);
            s2 += __expf(v[i + 2] - m);
            s3 += __expf(v[i + 3] - m);
            s4 += __expf(v[i + 4] - m);
        }
        float s = ((s0 + s1) + (s2 + s3)) + s4;
        alpha = m + __logf(s) + e;
    }

    float vv = (lane < 25) ? (alpha + en_s[lane]) : -1e30f;
    float mm = vv;
    for (int o = 16; o; o >>= 1) mm = fmaxf(mm, __shfl_xor_sync(0xffffffffu, mm, o));
    float ss = (lane < 25) ? __expf(vv - mm) : 0.f;
    for (int o = 16; o; o >>= 1) ss += __shfl_xor_sync(0xffffffffu, ss, o);
    float logZ = mm + __logf(ss);

    const int* lb = labels + b * T_;
    float acc = 0.f;
    for (int t = lane; t < T_; t += 32) {
        int lt = lb[t];
        float av = em_b[t * 25 + lt];
        if (t > 0) av += tr_s[lb[t - 1] * 26 + lt];
        acc += av;
    }
    for (int o = 16; o; o >>= 1) acc += __shfl_xor_sync(0xffffffffu, acc, o);

    if (lane == 0) {
        float num = acc + st_s[lb[0]] + en_s[lb[T_ - 1]];
        g_nll[b] = logZ - num;
    }
}

// =====================================================================
// Kernel 5: deterministic final reduction -> d_out[0]
// =====================================================================
__global__ __launch_bounds__(64) void k_sum(float* __restrict__ out)
{
    __shared__ float s[64];
    const int tid = threadIdx.x;
    s[tid] = g_nll[tid];
    __syncthreads();
    for (int o = 32; o; o >>= 1) {
        if (tid < o) s[tid] += s[tid + o];
        __syncthreads();
    }
    if (tid == 0) out[0] = s[0];
}

// =====================================================================
extern "C" void kernel_launch(void* const* d_in, const int* in_sizes, int n_in,
                              void* d_out, int out_size)
{
    const int*   sentence = (const int*)  d_in[0];
    const int*   labels   = (const int*)  d_in[1];
    // d_in[2] = mask (all ones)
    const float* emb      = (const float*)d_in[3];
    const float* w_ih_f   = (const float*)d_in[4];
    const float* w_hh_f   = (const float*)d_in[5];
    const float* b_ih_f   = (const float*)d_in[6];
    const float* b_hh_f   = (const float*)d_in[7];
    const float* w_ih_b   = (const float*)d_in[8];
    const float* w_hh_b   = (const float*)d_in[9];
    const float* b_ih_b   = (const float*)d_in[10];
    const float* b_hh_b   = (const float*)d_in[11];
    const float* W_out    = (const float*)d_in[12];
    const float* b_out    = (const float*)d_in[13];
    const float* start_t  = (const float*)d_in[14];
    const float* end_t    = (const float*)d_in[15];
    const float* trans    = (const float*)d_in[16];
    float* out = (float*)d_out;

    const int SMEM_LSTM = (64 * 260 + 64 * 18) * 4;    // 71168 B
    const int SMEM_EM   = (25 + 16) * 520 * 4;         // 85280 B
    cudaFuncSetAttribute(k_lstm, cudaFuncAttributeMaxDynamicSharedMemorySize, SMEM_LSTM);
    cudaFuncSetAttribute(k_em,   cudaFuncAttributeMaxDynamicSharedMemorySize, SMEM_EM);

    k_xg<<<dim3(2048 / 64, 16384 / 128), 256>>>(sentence, emb, w_ih_f, w_ih_b,
                                                b_ih_f, b_hh_f, b_ih_b, b_hh_b);
    k_lstm<<<128, 256, SMEM_LSTM>>>(w_hh_f, w_hh_b);
    k_em<<<256, 256, SMEM_EM>>>(W_out, b_out);
    k_crf<<<16, 128>>>(labels, start_t, end_t, trans);
    k_sum<<<1, 64>>>(out);
}

// round 17
// speedup vs baseline: 1.0158x; 1.0158x over previous
#include <cuda_runtime.h>
#include <cstdint>

#define T_ 256
#define B_ 64
#define E_ 300
#define H_ 256
#define G_ 1024
#define K_ 25

// ---------------- device scratch (static: no allocations allowed) ----------
__device__ float g_xg[2][T_][B_][G_];   // pre-activation gates
__device__ float g_h [2][T_][B_][H_];   // hidden states, both directions
__device__ float g_em[B_][T_][K_];      // emissions
__device__ float g_nll[B_];             // per-sequence (logZ - num)
__device__ unsigned g_bar_count[2];
__device__ volatile unsigned g_bar_phase[2];

__device__ __forceinline__ unsigned f2tf32(float f) {
    unsigned u; asm("cvt.rna.tf32.f32 %0, %1;" : "=r"(u) : "f"(f)); return u;
}

__device__ __forceinline__ void mma_tf32(
    float& c0, float& c1, float& c2, float& c3,
    unsigned a0, unsigned a1, unsigned a2, unsigned a3,
    unsigned b0, unsigned b1)
{
    asm volatile(
        "mma.sync.aligned.m16n8k8.row.col.f32.tf32.tf32.f32 "
        "{%0,%1,%2,%3},{%4,%5,%6,%7},{%8,%9},{%0,%1,%2,%3};"
        : "+f"(c0), "+f"(c1), "+f"(c2), "+f"(c3)
        : "r"(a0), "r"(a1), "r"(a2), "r"(a3), "r"(b0), "r"(b1));
}

// =====================================================================
// Kernel 1: embedding gather + xg GEMM — tf32 mma.sync (record source).
// C[16384 x 2048] = A[M,300] * W[N,300]^T, K padded to 320, BK=32.
// Also zeroes the k_lstm barrier state (stream-ordered).
// =====================================================================
__global__ __launch_bounds__(256) void k_xg(
    const int* __restrict__ sentence, const float* __restrict__ emb,
    const float* __restrict__ wf, const float* __restrict__ wb,
    const float* __restrict__ bihf, const float* __restrict__ bhhf,
    const float* __restrict__ bihb, const float* __restrict__ bhhb)
{
    __shared__ float A_s[128][36];   // tf32 bit patterns, pitch 36
    __shared__ float B_s[64][36];
    const int tid  = threadIdx.x;
    const int nblk = blockIdx.x * 64;
    const int mblk = blockIdx.y * 128;

    if (blockIdx.x == 0 && blockIdx.y == 0 && tid == 0) {
        g_bar_count[0] = 0u; g_bar_count[1] = 0u;
        g_bar_phase[0] = 0u; g_bar_phase[1] = 0u;
    }

    const int ar = tid >> 1;
    const int m_row = mblk + ar;
    const float* aptr = emb + (size_t)sentence[(m_row & 63) * T_ + (m_row >> 6)] * E_;

    const int wid = tid >> 5, lane = tid & 31;
    const int gid = lane >> 2, tig = lane & 3;
    const int wm = (wid >> 1) * 32;
    const int wn = (wid & 1) * 32;

    float acc[2][4][4];
    #pragma unroll
    for (int mi = 0; mi < 2; ++mi)
        #pragma unroll
        for (int ni = 0; ni < 4; ++ni)
            #pragma unroll
            for (int q = 0; q < 4; ++q) acc[mi][ni][q] = 0.f;

    for (int k0 = 0; k0 < 320; k0 += 32) {
        __syncthreads();
        #pragma unroll
        for (int q = 0; q < 4; ++q) {
            int kc = (tid & 1) * 16 + q * 4;
            int kg = k0 + kc;
            float4 v = make_float4(0.f, 0.f, 0.f, 0.f);
            if (kg + 4 <= E_) v = *(const float4*)(aptr + kg);
            A_s[ar][kc + 0] = __uint_as_float(f2tf32(v.x));
            A_s[ar][kc + 1] = __uint_as_float(f2tf32(v.y));
            A_s[ar][kc + 2] = __uint_as_float(f2tf32(v.z));
            A_s[ar][kc + 3] = __uint_as_float(f2tf32(v.w));
        }
        #pragma unroll
        for (int i2 = 0; i2 < 2; ++i2) {
            int i  = tid + i2 * 256;
            int br = i >> 3;
            int kc = (i & 7) * 4;
            int n  = nblk + br;
            const float* bp = (n < G_) ? (wf + (size_t)n * E_)
                                       : (wb + (size_t)(n - G_) * E_);
            int kg = k0 + kc;
            float4 v = make_float4(0.f, 0.f, 0.f, 0.f);
            if (kg + 4 <= E_) v = *(const float4*)(bp + kg);
            B_s[br][kc + 0] = __uint_as_float(f2tf32(v.x));
            B_s[br][kc + 1] = __uint_as_float(f2tf32(v.y));
            B_s[br][kc + 2] = __uint_as_float(f2tf32(v.z));
            B_s[br][kc + 3] = __uint_as_float(f2tf32(v.w));
        }
        __syncthreads();

        #pragma unroll
        for (int s = 0; s < 4; ++s) {
            int kk = s * 8;
            unsigned a[2][4];
            #pragma unroll
            for (int mi = 0; mi < 2; ++mi) {
                const float* ap0 = &A_s[wm + 16 * mi + gid][kk + tig];
                const float* ap1 = &A_s[wm + 16 * mi + gid + 8][kk + tig];
                a[mi][0] = __float_as_uint(ap0[0]);
                a[mi][1] = __float_as_uint(ap1[0]);
                a[mi][2] = __float_as_uint(ap0[4]);
                a[mi][3] = __float_as_uint(ap1[4]);
            }
            unsigned bf[4][2];
            #pragma unroll
            for (int ni = 0; ni < 4; ++ni) {
                const float* bp = &B_s[wn + 8 * ni + gid][kk + tig];
                bf[ni][0] = __float_as_uint(bp[0]);
                bf[ni][1] = __float_as_uint(bp[4]);
            }
            #pragma unroll
            for (int mi = 0; mi < 2; ++mi)
                #pragma unroll
                for (int ni = 0; ni < 4; ++ni)
                    mma_tf32(acc[mi][ni][0], acc[mi][ni][1],
                             acc[mi][ni][2], acc[mi][ni][3],
                             a[mi][0], a[mi][1], a[mi][2], a[mi][3],
                             bf[ni][0], bf[ni][1]);
        }
    }

    const int dirn = nblk >> 10;
    const int gnb  = nblk & 1023;
    const float* bi = dirn ? bihb : bihf;
    const float* bh = dirn ? bhhb : bhhf;
    float* base = &g_xg[dirn][0][0][0];

    float2 bias2[4];
    #pragma unroll
    for (int ni = 0; ni < 4; ++ni) {
        int gb = gnb + wn + 8 * ni + 2 * tig;
        bias2[ni] = make_float2(bi[gb] + bh[gb], bi[gb + 1] + bh[gb + 1]);
    }

    #pragma unroll
    for (int mi = 0; mi < 2; ++mi) {
        int m0r = mblk + wm + 16 * mi + gid;
        #pragma unroll
        for (int ni = 0; ni < 4; ++ni) {
            int gn = gnb + wn + 8 * ni + 2 * tig;
            float2 v0 = make_float2(acc[mi][ni][0] + bias2[ni].x,
                                    acc[mi][ni][1] + bias2[ni].y);
            float2 v1 = make_float2(acc[mi][ni][2] + bias2[ni].x,
                                    acc[mi][ni][3] + bias2[ni].y);
            *(float2*)(base + (size_t)m0r * G_ + gn)       = v0;
            *(float2*)(base + (size_t)(m0r + 8) * G_ + gn) = v1;
        }
    }
}

// =====================================================================
// Kernel 2: persistent BiLSTM recurrence — tf32 mma.sync, 64 blocks/dir,
// W fragments in registers, pipelined tf32 h staging, atomic-counter
// grid barrier. (Record source.)
// =====================================================================
__device__ __forceinline__ float sigmoidf_(float x) {
    return 1.f / (1.f + __expf(-x));
}

__global__ __launch_bounds__(256, 1) void k_lstm(
    const float* __restrict__ whf, const float* __restrict__ whb)
{
    extern __shared__ float sm[];
    float* h_s = sm;              // [64][260] tf32-truncated h values
    float* Y_s = sm + 64 * 260;   // [64][18]  gate pre-activations
    const int tid = threadIdx.x;
    const int dir = blockIdx.x >> 6;
    const int cbk = blockIdx.x & 63;
    const int c0  = cbk * 4;
    const float* wh = dir ? whb : whf;

    const int wid = tid >> 5, lane = tid & 31;
    const int gid = lane >> 2, tig = lane & 3;
    const int m0 = (wid >> 1) * 16;    // warp's 16 batch rows
    const int n0 = (wid & 1) * 8;      // warp's 8 local gate cols

    const int l = n0 + gid;
    const float* wr = wh + (size_t)((l >> 2) * 256 + c0 + (l & 3)) * H_;
    unsigned wb0[32], wb1[32];
    #pragma unroll
    for (int s = 0; s < 32; ++s) {
        wb0[s] = f2tf32(__ldg(wr + s * 8 + tig));
        wb1[s] = f2tf32(__ldg(wr + s * 8 + tig + 4));
    }

    const int b = tid >> 2, c = tid & 3;
    float creg = 0.f;
    unsigned phase = 0;

    for (int step = 0; step < T_; ++step) {
        const int t = dir ? (T_ - 1 - step) : step;

        const float* xg = &g_xg[dir][t][b][0];
        float ai = __ldg(xg +       c0 + c);
        float af = __ldg(xg + 256 + c0 + c);
        float ag = __ldg(xg + 512 + c0 + c);
        float ao = __ldg(xg + 768 + c0 + c);

        float acc0 = 0.f, acc1 = 0.f, acc2 = 0.f, acc3 = 0.f;

        if (step > 0) {
            const int tp = dir ? (t + 1) : (t - 1);
            const float4* src = (const float4*)&g_h[dir][tp][0][0];
            float4 pre[4];
            #pragma unroll
            for (int q = 0; q < 4; ++q) {
                int u = q * 256 + tid;
                pre[q] = __ldcg(src + (u >> 4) * 64 + (u & 15));
            }
            #pragma unroll
            for (int cc = 0; cc < 4; ++cc) {
                #pragma unroll
                for (int q = 0; q < 4; ++q) {
                    int u = q * 256 + tid;
                    float4 v = pre[q];
                    float4 w;
                    w.x = __uint_as_float(f2tf32(v.x));
                    w.y = __uint_as_float(f2tf32(v.y));
                    w.z = __uint_as_float(f2tf32(v.z));
                    w.w = __uint_as_float(f2tf32(v.w));
                    *(float4*)&h_s[(u >> 4) * 260 + cc * 64 + (u & 15) * 4] = w;
                }
                float4 nxt[4];
                if (cc < 3) {
                    #pragma unroll
                    for (int q = 0; q < 4; ++q) {
                        int u = q * 256 + tid;
                        nxt[q] = __ldcg(src + (u >> 4) * 64 + (cc + 1) * 16 + (u & 15));
                    }
                }
                __syncthreads();
                #pragma unroll
                for (int s = 0; s < 8; ++s) {
                    int kk = cc * 64 + s * 8;
                    const float* ar = &h_s[(m0 + gid) * 260 + kk + tig];
                    unsigned a0 = __float_as_uint(ar[0]);
                    unsigned a2 = __float_as_uint(ar[4]);
                    unsigned a1 = __float_as_uint(ar[8 * 260]);
                    unsigned a3 = __float_as_uint(ar[8 * 260 + 4]);
                    int si = cc * 8 + s;
                    mma_tf32(acc0, acc1, acc2, acc3, a0, a1, a2, a3, wb0[si], wb1[si]);
                }
                #pragma unroll
                for (int q = 0; q < 4; ++q) pre[q] = nxt[q];
            }
            *(float2*)&Y_s[(m0 + gid) * 18 + n0 + 2 * tig]     = make_float2(acc0, acc1);
            *(float2*)&Y_s[(m0 + gid + 8) * 18 + n0 + 2 * tig] = make_float2(acc2, acc3);
        }
        __syncthreads();

        if (step > 0) {
            ai += Y_s[b * 18 +      c];
            af += Y_s[b * 18 +  4 + c];
            ag += Y_s[b * 18 +  8 + c];
            ao += Y_s[b * 18 + 12 + c];
        }

        float si = sigmoidf_(ai);
        float sf = sigmoidf_(af);
        float so = sigmoidf_(ao);
        float tg = tanhf(ag);
        creg = sf * creg + si * tg;
        g_h[dir][t][b][c0 + c] = so * tanhf(creg);

        // ---- atomic-counter grid barrier (per direction, 64 blocks) ----
        __syncthreads();
        if (tid == 0) {
            __threadfence();
            unsigned p = phase + 1;
            if (atomicAdd(&g_bar_count[dir], 1u) == 63u) {
                g_bar_count[dir] = 0u;
                __threadfence();
                g_bar_phase[dir] = p;
            } else {
                while (g_bar_phase[dir] < p) { }
                __threadfence();
            }
        }
        __syncthreads();
        phase++;
    }
}

// =====================================================================
// Kernel 3: emissions em[b][t][k] = [hf|hb] . W_out[k] + b_out[k]
// =====================================================================
__global__ __launch_bounds__(256) void k_em(
    const float* __restrict__ Wout, const float* __restrict__ bout)
{
    extern __shared__ float sm[];
    float* W_s = sm;              // [25][520]
    float* h_s = sm + 25 * 520;   // [16][520]
    const int tid = threadIdx.x;
    const int t = blockIdx.x;

    for (int i = tid; i < 25 * 512; i += 256) {
        int k = i >> 9, j = i & 511;
        W_s[k * 520 + j] = Wout[(size_t)k * 512 + j];
    }
    for (int bg = 0; bg < 4; ++bg) {
        __syncthreads();
        for (int i = tid; i < 16 * 512; i += 256) {
            int bb = i >> 9, j = i & 511;
            int bglob = bg * 16 + bb;
            float v = (j < 256) ? g_h[0][t][bglob][j] : g_h[1][t][bglob][j - 256];
            h_s[bb * 520 + j] = v;
        }
        __syncthreads();
        for (int idx = tid; idx < 16 * 25; idx += 256) {
            int bb = idx / 25, k = idx % 25;
            const float* hr = &h_s[bb * 520];
            const float* wr = &W_s[k * 520];
            float dot = 0.f;
            #pragma unroll 8
            for (int j = 0; j < 512; j += 4) {
                float4 hv = *(const float4*)(hr + j);
                float4 wv = *(const float4*)(wr + j);
                dot += hv.x * wv.x + hv.y * wv.y + hv.z * wv.z + hv.w * wv.w;
            }
            g_em[bg * 16 + bb][t][k] = dot + bout[k];
        }
    }
}

// =====================================================================
// Kernel 4: CRF — R3 version (best measured: 135-138us across 6 runs).
// =====================================================================
__global__ __launch_bounds__(128) void k_crf(
    const int* __restrict__ labels,
    const float* __restrict__ start_t,
    const float* __restrict__ end_t,
    const float* __restrict__ trans)
{
    __shared__ float tr_s[25 * 26 + 8];
    __shared__ float st_s[25], en_s[25];
    const int tid = threadIdx.x;
    for (int i = tid; i < 625; i += 128)
        tr_s[(i / 25) * 26 + (i % 25)] = trans[i];
    if (tid < 25) { st_s[tid] = start_t[tid]; en_s[tid] = end_t[tid]; }
    __syncthreads();

    const int w = tid >> 5, lane = tid & 31;
    const int b = blockIdx.x * 4 + w;
    const int lj = (lane < 25) ? lane : 24;
    const float* em_b = &g_em[b][0][0];

    float alpha = (lane < 25) ? (st_s[lane] + em_b[lane]) : -1e30f;

    for (int t = 1; t < T_; ++t) {
        float e = (lane < 25) ? em_b[t * 25 + lane] : 0.f;
        float m = -1e30f;
        #pragma unroll
        for (int i = 0; i < 25; ++i) {
            float ai = __shfl_sync(0xffffffffu, alpha, i);
            m = fmaxf(m, ai + tr_s[i * 26 + lj]);
        }
        float s = 0.f;
        #pragma unroll
        for (int i = 0; i < 25; ++i) {
            float ai = __shfl_sync(0xffffffffu, alpha, i);
            s += __expf(ai + tr_s[i * 26 + lj] - m);
        }
        alpha = m + __logf(s) + e;
    }

    float v = (lane < 25) ? (alpha + en_s[lane]) : -1e30f;
    float m = v;
    for (int o = 16; o; o >>= 1) m = fmaxf(m, __shfl_xor_sync(0xffffffffu, m, o));
    float s = (lane < 25) ? __expf(v - m) : 0.f;
    for (int o = 16; o; o >>= 1) s += __shfl_xor_sync(0xffffffffu, s, o);
    float logZ = m + __logf(s);

    const int* lb = labels + b * T_;
    float acc = 0.f;
    for (int t = lane; t < T_; t += 32) {
        int lt = lb[t];
        float vv = em_b[t * 25 + lt];
        if (t > 0) vv += tr_s[lb[t - 1] * 26 + lt];
        acc += vv;
    }
    for (int o = 16; o; o >>= 1) acc += __shfl_xor_sync(0xffffffffu, acc, o);

    if (lane == 0) {
        float num = acc + st_s[lb[0]] + en_s[lb[T_ - 1]];
        g_nll[b] = logZ - num;
    }
}

// =====================================================================
// Kernel 5: deterministic final reduction -> d_out[0]
// =====================================================================
__global__ __launch_bounds__(64) void k_sum(float* __restrict__ out)
{
    __shared__ float s[64];
    const int tid = threadIdx.x;
    s[tid] = g_nll[tid];
    __syncthreads();
    for (int o = 32; o; o >>= 1) {
        if (tid < o) s[tid] += s[tid + o];
        __syncthreads();
    }
    if (tid == 0) out[0] = s[0];
}

// =====================================================================
extern "C" void kernel_launch(void* const* d_in, const int* in_sizes, int n_in,
                              void* d_out, int out_size)
{
    const int*   sentence = (const int*)  d_in[0];
    const int*   labels   = (const int*)  d_in[1];
    // d_in[2] = mask (all ones)
    const float* emb      = (const float*)d_in[3];
    const float* w_ih_f   = (const float*)d_in[4];
    const float* w_hh_f   = (const float*)d_in[5];
    const float* b_ih_f   = (const float*)d_in[6];
    const float* b_hh_f   = (const float*)d_in[7];
    const float* w_ih_b   = (const float*)d_in[8];
    const float* w_hh_b   = (const float*)d_in[9];
    const float* b_ih_b   = (const float*)d_in[10];
    const float* b_hh_b   = (const float*)d_in[11];
    const float* W_out    = (const float*)d_in[12];
    const float* b_out    = (const float*)d_in[13];
    const float* start_t  = (const float*)d_in[14];
    const float* end_t    = (const float*)d_in[15];
    const float* trans    = (const float*)d_in[16];
    float* out = (float*)d_out;

    const int SMEM_LSTM = (64 * 260 + 64 * 18) * 4;    // 71168 B
    const int SMEM_EM   = (25 + 16) * 520 * 4;         // 85280 B
    cudaFuncSetAttribute(k_lstm, cudaFuncAttributeMaxDynamicSharedMemorySize, SMEM_LSTM);
    cudaFuncSetAttribute(k_em,   cudaFuncAttributeMaxDynamicSharedMemorySize, SMEM_EM);

    k_xg<<<dim3(2048 / 64, 16384 / 128), 256>>>(sentence, emb, w_ih_f, w_ih_b,
                                                b_ih_f, b_hh_f, b_ih_b, b_hh_b);
    k_lstm<<<128, 256, SMEM_LSTM>>>(w_hh_f, w_hh_b);
    k_em<<<256, 256, SMEM_EM>>>(W_out, b_out);
    k_crf<<<16, 128>>>(labels, start_t, end_t, trans);
    k_sum<<<1, 64>>>(out);
}